// round 5
// baseline (speedup 1.0000x reference)
#include <cuda_runtime.h>
#include <math.h>

#define NN 50000
#define EE 1600000
#define GG 64
#define NODE_IN 32
#define HID 64
#define EDGE_IN 16
#define NLAYER 3

typedef unsigned long long ull;

// ---------------- device scratch (static globals; no runtime alloc) ----------------
__device__ float d_h[NN * HID];
__device__ float d_qn[NN * HID];
__device__ float d_kn[NN * HID];
__device__ float d_vn[NN * HID];
__device__ float d_sn[NN * HID];
__device__ float d_qwn[NN * HID];   // per-node q.We projection (4 heads x 16 r, packed)
__device__ int   d_deg[NN];
__device__ int   d_offs[NN + 1];
__device__ int   d_cursor[NN];
__device__ int   d_bsum[64];
__device__ int   d_ssrc[EE];        // src sorted by dst
__device__ int   d_seid[EE];        // original edge id sorted by dst
__device__ float d_sea[(size_t)EE * EDGE_IN];   // permuted edge_attr (coalesced in loop)
__device__ float d_M[HID * HID];    // fused Wq x We matrix for qw GEMM
__device__ float d_bqw[HID];

__device__ __forceinline__ float ex2(float x) {
    float r;
    asm("ex2.approx.f32 %0, %1;" : "=f"(r) : "f"(x));
    return r;
}
__device__ __forceinline__ ull pack2(float a, float b) {
    ull r;
    asm("mov.b64 %0, {%1, %2};" : "=l"(r) : "f"(a), "f"(b));
    return r;
}
__device__ __forceinline__ void unpack2(float& a, float& b, ull v) {
    asm("mov.b64 {%0, %1}, %2;" : "=f"(a), "=f"(b) : "l"(v));
}
__device__ __forceinline__ ull fma2(ull a, ull b, ull c) {
    ull r;
    asm("fma.rn.f32x2 %0, %1, %2, %3;" : "=l"(r) : "l"(a), "l"(b), "l"(c));
    return r;
}
__device__ __forceinline__ ull mul2(ull a, ull b) {
    ull r;
    asm("mul.rn.f32x2 %0, %1, %2;" : "=l"(r) : "l"(a), "l"(b));
    return r;
}

// ---------------- preprocessing: counting sort of edges by dst ----------------
__global__ void zero_deg_kernel() {
    int i = blockIdx.x * blockDim.x + threadIdx.x;
    if (i < NN) d_deg[i] = 0;
}

__global__ void hist_kernel(const int* __restrict__ ei) {
    int e = blockIdx.x * blockDim.x + threadIdx.x;
    if (e < EE) atomicAdd(&d_deg[ei[EE + e]], 1);
}

__global__ void scan1_kernel() {
    __shared__ int s[1024];
    int t = threadIdx.x;
    int i = blockIdx.x * 1024 + t;
    int v = (i < NN) ? d_deg[i] : 0;
    s[t] = v;
    __syncthreads();
    for (int o = 1; o < 1024; o <<= 1) {
        int x = (t >= o) ? s[t - o] : 0;
        __syncthreads();
        s[t] += x;
        __syncthreads();
    }
    if (i < NN) d_offs[i] = s[t] - v;
    if (t == 1023) d_bsum[blockIdx.x] = s[t];
}

__global__ void scan2_kernel(int nb) {
    if (threadIdx.x == 0 && blockIdx.x == 0) {
        int run = 0;
        for (int b = 0; b < nb; b++) { int tmp = d_bsum[b]; d_bsum[b] = run; run += tmp; }
        d_offs[NN] = run;
    }
}

__global__ void scan3_kernel() {
    int i = blockIdx.x * blockDim.x + threadIdx.x;
    if (i < NN) {
        int v = d_offs[i] + d_bsum[i >> 10];
        d_offs[i] = v;
        d_cursor[i] = v;
    }
}

__global__ void scatter_kernel(const int* __restrict__ ei) {
    int e = blockIdx.x * blockDim.x + threadIdx.x;
    if (e < EE) {
        int dstv = ei[EE + e];
        int pos = atomicAdd(&d_cursor[dstv], 1);
        d_ssrc[pos] = ei[e];
        d_seid[pos] = e;
    }
}

__global__ void permute_ea_kernel(const float* __restrict__ ea) {
    int t = blockIdx.x * blockDim.x + threadIdx.x;
    if (t < EE * 4) {
        int pos = t >> 2;
        int u = t & 3;
        int eid = d_seid[pos];
        float4 v = reinterpret_cast<const float4*>(ea)[(size_t)eid * 4 + u];
        reinterpret_cast<float4*>(d_sea)[(size_t)pos * 4 + u] = v;
    }
}

// ---------------- input embedding: h = relu(x @ Wn + bn) ----------------
__global__ __launch_bounds__(256) void node_in_kernel(const float* __restrict__ x,
                                                      const float* __restrict__ Wn,
                                                      const float* __restrict__ bn) {
    __shared__ float Wns[NODE_IN * HID];
    __shared__ float bns[HID];
    __shared__ float xs[4][NODE_IN];
    int t = threadIdx.x;
    for (int u = t; u < NODE_IN * HID; u += 256) Wns[u] = Wn[u];
    if (t < HID) bns[t] = bn[t];
    int j = t & 63, y = t >> 6;
    int node = blockIdx.x * 4 + y;
    if (j < NODE_IN && node < NN) xs[y][j] = x[node * NODE_IN + j];
    __syncthreads();
    if (node < NN) {
        float a = bns[j];
        #pragma unroll
        for (int k = 0; k < NODE_IN; k++) a += xs[y][k] * Wns[k * HID + j];
        d_h[(size_t)node * HID + j] = fmaxf(a, 0.f);
    }
}

// ---------------- per-layer M = per-head (Wq x We), bqw = per-head (bq x We) ------
__global__ void prep_M_kernel(const float* __restrict__ Wq, const float* __restrict__ bq,
                              const float* __restrict__ We, int layer) {
    int idx = blockIdx.x * 256 + threadIdx.x;
    const float* Wql = Wq + layer * HID * HID;
    const float* Wel = We + layer * EDGE_IN * HID;
    if (idx < HID * HID) {
        int krow = idx >> 6, col = idx & 63;
        int h = col >> 4, r = col & 15;
        float s = 0.f;
        #pragma unroll
        for (int c = 0; c < 16; c++)
            s += Wql[krow * HID + h * 16 + c] * Wel[r * HID + h * 16 + c];
        d_M[idx] = s;
    }
    if (idx < HID) {
        int h = idx >> 4, r = idx & 15;
        const float* bql = bq + layer * HID;
        float s = 0.f;
        #pragma unroll
        for (int c = 0; c < 16; c++)
            s += bql[h * 16 + c] * Wel[r * HID + h * 16 + c];
        d_bqw[idx] = s;
    }
}

// ---------------- fused Q/K/V/Skip/QW node GEMM, f32x2 packed FMA ----------------
// 64 nodes x 320 cols per block. Thread (ry=warp, cx=lane) owns rows ry*8..+7 and
// col pairs {64*c2 + 2*cx, +1}, c2=0..4 -> matrix index = c2 directly.
__global__ __launch_bounds__(256, 1) void qkvs_kernel(
    const float* __restrict__ Wq, const float* __restrict__ bq,
    const float* __restrict__ Wk, const float* __restrict__ bk,
    const float* __restrict__ Wv, const float* __restrict__ bv,
    const float* __restrict__ Ws, const float* __restrict__ bs, int layer) {
    extern __shared__ float sm[];
    float* hs = sm;            // 64 x 64
    float* ws = sm + 64 * 64;  // 64 x 320 (Q|K|V|S|M blocks of 64 cols)
    const float* Wm[5] = {Wq + layer * HID * HID, Wk + layer * HID * HID,
                          Wv + layer * HID * HID, Ws + layer * HID * HID, d_M};
    const float* bm[5] = {bq + layer * HID, bk + layer * HID, bv + layer * HID,
                          bs + layer * HID, d_bqw};
    float* outp[5] = {d_qn, d_kn, d_vn, d_sn, d_qwn};
    int t = threadIdx.x;
    int node0 = blockIdx.x * 64;

    #pragma unroll
    for (int u = 0; u < 20; u++) {
        int mat = u >> 2;
        int e0 = ((u & 3) * 256 + t) * 4;
        int k = e0 >> 6, jj = e0 & 63;
        float4 w4 = *reinterpret_cast<const float4*>(Wm[mat] + k * HID + jj);
        *reinterpret_cast<float4*>(ws + k * 320 + mat * 64 + jj) = w4;
    }
    #pragma unroll
    for (int u = 0; u < 4; u++) {
        int e0 = (u * 256 + t) * 4;
        int row = e0 >> 6, k = e0 & 63;
        int node = node0 + row;
        float4 h4 = make_float4(0.f, 0.f, 0.f, 0.f);
        if (node < NN) h4 = *reinterpret_cast<const float4*>(d_h + (size_t)node * HID + k);
        *reinterpret_cast<float4*>(hs + e0) = h4;
    }
    __syncthreads();

    int ry = t >> 5;
    int cx = t & 31;
    ull accp[8][5];
    #pragma unroll
    for (int c2 = 0; c2 < 5; c2++) {
        float2 b2v = *reinterpret_cast<const float2*>(bm[c2] + 2 * cx);
        ull b = pack2(b2v.x, b2v.y);
        #pragma unroll
        for (int rr = 0; rr < 8; rr++) accp[rr][c2] = b;
    }
    #pragma unroll 4
    for (int k0 = 0; k0 < 64; k0 += 4) {
        float4 hr4[8];
        #pragma unroll
        for (int rr = 0; rr < 8; rr++)
            hr4[rr] = *reinterpret_cast<const float4*>(hs + (ry * 8 + rr) * 64 + k0);
        const float* hrf = reinterpret_cast<const float*>(hr4);
        #pragma unroll
        for (int kk = 0; kk < 4; kk++) {
            ull wp[5];
            #pragma unroll
            for (int c2 = 0; c2 < 5; c2++)
                wp[c2] = *reinterpret_cast<const ull*>(ws + (k0 + kk) * 320 + c2 * 64 + 2 * cx);
            #pragma unroll
            for (int rr = 0; rr < 8; rr++) {
                float hv = hrf[rr * 4 + kk];
                ull hd = pack2(hv, hv);
                #pragma unroll
                for (int c2 = 0; c2 < 5; c2++)
                    accp[rr][c2] = fma2(hd, wp[c2], accp[rr][c2]);
            }
        }
    }
    #pragma unroll
    for (int rr = 0; rr < 8; rr++) {
        int node = node0 + ry * 8 + rr;
        if (node >= NN) continue;
        #pragma unroll
        for (int c2 = 0; c2 < 5; c2++) {
            float lo, hi;
            unpack2(lo, hi, accp[rr][c2]);
            *reinterpret_cast<float2*>(outp[c2] + (size_t)node * HID + 2 * cx) =
                make_float2(lo, hi);
        }
    }
}

// ---------------- fused attention: half-warp per edge, warp per node -------------
// lane = 16*hf + 4*head + p ; lane owns channels (4h+p)*4..+3, edge-feats p*4..+3.
// Two parallel softmax streams (one per half), merged at the end. Warp-uniform
// trip count; trailing invalid slot clamps loads and contributes w=0.
// src prefetched 2 iterations ahead; K/V/E one ahead. f32x2 packed math.
__global__ __launch_bounds__(256) void attn_kernel(const float* __restrict__ We,
                                                   int layer) {
    __shared__ float WeS[16 * 68 + 4];  // skewed: [r*68 + col + (col>>4)]
    int t = threadIdx.x;
    const float* Wel = We + layer * EDGE_IN * HID;
    for (int u = t; u < EDGE_IN * HID; u += 256) {
        int r = u >> 6, col = u & 63;
        WeS[r * 68 + col + (col >> 4)] = Wel[u];
    }
    __syncthreads();

    int lane = t & 31;
    int warp = t >> 5;
    int n = blockIdx.x * 8 + warp;
    if (n >= NN) return;

    int hf = lane >> 4;
    int hl = lane & 15;
    int h = hl >> 2;
    int p = hl & 3;
    int cbs = hl * 4 + h;

    const ulonglong2* kn2 = reinterpret_cast<const ulonglong2*>(d_kn);
    const ulonglong2* vn2 = reinterpret_cast<const ulonglong2*>(d_vn);
    const ulonglong2* ea2 = reinterpret_cast<const ulonglong2*>(d_sea);

    ulonglong2 q2  = reinterpret_cast<const ulonglong2*>(d_qn)[n * 16 + hl];
    ulonglong2 qw2 = reinterpret_cast<const ulonglong2*>(d_qwn)[n * 16 + hl];

    float m = -1e30f, den = 0.f;
    ull accp0 = 0, accp1 = 0, eacp0 = 0, eacp1 = 0;

    int beg = d_offs[n], end = d_offs[n + 1];
    int d = end - beg;
    int itmax = (d + 1) >> 1;          // warp-uniform trip count

    int i = beg + hf;
    bool vld_cur = (i < end);
    bool vld_nxt = (i + 2 < end);
    int src_nxt = 0;
    ulonglong2 k2, v2, e2;
    if (itmax > 0) {
        int idx = vld_cur ? i : (end - 1);
        int src = d_ssrc[idx];
        k2 = kn2[src * 16 + hl];
        v2 = vn2[src * 16 + hl];
        e2 = ea2[idx * 4 + p];
        if (itmax > 1) {
            int idx2 = vld_nxt ? (i + 2) : (end - 1);
            src_nxt = d_ssrc[idx2];
        }
    }
    for (int it = 0; it < itmax; it++) {
        ulonglong2 ck = k2, cv = v2, ce = e2;
        bool cvld = vld_cur;
        if (it + 1 < itmax) {
            int ii = i + 2;
            k2 = kn2[src_nxt * 16 + hl];
            v2 = vn2[src_nxt * 16 + hl];
            int idx2 = vld_nxt ? ii : (end - 1);
            e2 = ea2[idx2 * 4 + p];
            vld_cur = vld_nxt;
            int i3 = ii + 2;
            bool v3 = (i3 < end);
            int idx3 = v3 ? i3 : (end - 1);
            src_nxt = d_ssrc[idx3];
            vld_nxt = v3;
            i = ii;
        }
        // score: q.k + qw.e via packed f32x2
        ull dp = mul2(q2.x, ck.x);
        dp = fma2(q2.y, ck.y, dp);
        dp = fma2(qw2.x, ce.x, dp);
        dp = fma2(qw2.y, ce.y, dp);
        float dlo, dhi;
        unpack2(dlo, dhi, dp);
        float pp = dlo + dhi;
        pp += __shfl_xor_sync(0xffffffffu, pp, 1);
        pp += __shfl_xor_sync(0xffffffffu, pp, 2);
        pp = cvld ? pp * 0.36067376022224085f : -1e30f;   // 0.25*log2(e); -inf if invalid
        float w;
        if (cvld && pp > m) {          // new running max (rare)
            float sc = ex2(m - pp);
            m = pp;
            den *= sc;
            ull scp = pack2(sc, sc);
            accp0 = mul2(scp, accp0); accp1 = mul2(scp, accp1);
            eacp0 = mul2(scp, eacp0); eacp1 = mul2(scp, eacp1);
            w = 1.0f;
        } else {
            w = ex2(pp - m);
            w = cvld ? w : 0.f;
        }
        den += w;
        ull wpk = pack2(w, w);
        accp0 = fma2(wpk, cv.x, accp0);
        accp1 = fma2(wpk, cv.y, accp1);
        eacp0 = fma2(wpk, ce.x, eacp0);
        eacp1 = fma2(wpk, ce.y, eacp1);
    }

    float4 acc, eac;
    unpack2(acc.x, acc.y, accp0); unpack2(acc.z, acc.w, accp1);
    unpack2(eac.x, eac.y, eacp0); unpack2(eac.z, eac.w, eacp1);

    // fold edge-embedding: acc[c] += sum_r eacc[h][r] * We[r][c]   (conflict-free smem)
    float ea_arr[4] = {eac.x, eac.y, eac.z, eac.w};
    #pragma unroll
    for (int r = 0; r < 16; r++) {
        float ev = __shfl_sync(0xffffffffu, ea_arr[r & 3], (h << 2) + (r >> 2), 16);
        acc.x += ev * WeS[r * 68 + cbs + 0];
        acc.y += ev * WeS[r * 68 + cbs + 1];
        acc.z += ev * WeS[r * 68 + cbs + 2];
        acc.w += ev * WeS[r * 68 + cbs + 3];
    }

    // merge the two half-warp softmax streams
    float om  = __shfl_xor_sync(0xffffffffu, m,    16);
    float odn = __shfl_xor_sync(0xffffffffu, den,  16);
    float oax = __shfl_xor_sync(0xffffffffu, acc.x, 16);
    float oay = __shfl_xor_sync(0xffffffffu, acc.y, 16);
    float oaz = __shfl_xor_sync(0xffffffffu, acc.z, 16);
    float oaw = __shfl_xor_sync(0xffffffffu, acc.w, 16);
    float mm = fmaxf(m, om);
    float sA = ex2(m - mm), sB = ex2(om - mm);
    den = den * sA + odn * sB;
    float ox = acc.x * sA + oax * sB;
    float oy = acc.y * sA + oay * sB;
    float oz = acc.z * sA + oaz * sB;
    float ow = acc.w * sA + oaw * sB;

    if (hf == 0) {
        float inv = 1.f / (den + 1e-16f);
        float4 s4 = reinterpret_cast<const float4*>(d_sn)[n * 16 + hl];
        float4 hc = reinterpret_cast<const float4*>(d_h)[n * 16 + hl];
        hc.x += fmaxf(ox * inv + s4.x, 0.f);
        hc.y += fmaxf(oy * inv + s4.y, 0.f);
        hc.z += fmaxf(oz * inv + s4.z, 0.f);
        hc.w += fmaxf(ow * inv + s4.w, 0.f);
        reinterpret_cast<float4*>(d_h)[n * 16 + hl] = hc;
    }
}

// ---------------- fused mean pool (sorted batch) + readout MLP -------------------
__global__ __launch_bounds__(1024) void pool_mlp_kernel(const int* __restrict__ batch,
    const float* __restrict__ W1, const float* __restrict__ b1,
    const float* __restrict__ W2, const float* __restrict__ b2,
    float* __restrict__ out) {
    __shared__ float red[1024];
    __shared__ float sp[64];
    __shared__ int bnd[2];
    int g = blockIdx.x, t = threadIdx.x;
    if (t == 0) {
        int lo = 0, hi = NN;
        while (lo < hi) { int mid = (lo + hi) >> 1; if (batch[mid] < g) lo = mid + 1; else hi = mid; }
        bnd[0] = lo;
        int lo2 = lo, hi2 = NN;
        while (lo2 < hi2) { int mid = (lo2 + hi2) >> 1; if (batch[mid] < g + 1) lo2 = mid + 1; else hi2 = mid; }
        bnd[1] = lo2;
    }
    __syncthreads();
    int lo = bnd[0], hi = bnd[1];
    int ch = t & 63, rg = t >> 6;     // 16 row groups
    float a = 0.f;
    for (int nd = lo + rg; nd < hi; nd += 16) a += d_h[(size_t)nd * HID + ch];
    red[t] = a;
    __syncthreads();
    if (t < 64) {
        float s = 0.f;
        #pragma unroll
        for (int j = 0; j < 16; j++) s += red[t + 64 * j];
        sp[t] = s / fmaxf((float)(hi - lo), 1.0f);
    }
    __syncthreads();
    if (t < 32) {
        float accv = b1[t];
        #pragma unroll
        for (int k = 0; k < HID; k++) accv += sp[k] * W1[k * 32 + t];
        float v = fmaxf(accv, 0.f) * W2[t];
        #pragma unroll
        for (int o = 16; o; o >>= 1) v += __shfl_xor_sync(0xffffffffu, v, o);
        if (t == 0) out[g] = v + b2[0];
    }
}

// ---------------- launch ----------------
extern "C" void kernel_launch(void* const* d_in, const int* in_sizes, int n_in,
                              void* d_out, int out_size) {
    const float* x   = (const float*)d_in[0];
    const int*   ei  = (const int*)d_in[1];
    const float* ea  = (const float*)d_in[2];
    const int*   bat = (const int*)d_in[3];
    const float* Wn  = (const float*)d_in[4];
    const float* bn  = (const float*)d_in[5];
    const float* Wq  = (const float*)d_in[6];
    const float* bq  = (const float*)d_in[7];
    const float* Wk  = (const float*)d_in[8];
    const float* bk  = (const float*)d_in[9];
    const float* Wv  = (const float*)d_in[10];
    const float* bv  = (const float*)d_in[11];
    const float* We  = (const float*)d_in[12];
    const float* Ws  = (const float*)d_in[13];
    const float* bs  = (const float*)d_in[14];
    const float* W1  = (const float*)d_in[15];
    const float* b1  = (const float*)d_in[16];
    const float* W2  = (const float*)d_in[17];
    const float* b2  = (const float*)d_in[18];
    float* out = (float*)d_out;

    cudaFuncSetAttribute(qkvs_kernel, cudaFuncAttributeMaxDynamicSharedMemorySize, 100 * 1024);

    // 1) counting sort of edges by dst -> CSR of src/eid + permuted edge_attr
    zero_deg_kernel<<<(NN + 255) / 256, 256>>>();
    hist_kernel<<<(EE + 255) / 256, 256>>>(ei);
    int nb = (NN + 1023) / 1024;
    scan1_kernel<<<nb, 1024>>>();
    scan2_kernel<<<1, 32>>>(nb);
    scan3_kernel<<<(NN + 255) / 256, 256>>>();
    scatter_kernel<<<(EE + 255) / 256, 256>>>(ei);
    permute_ea_kernel<<<(EE * 4 + 255) / 256, 256>>>(ea);

    // 2) input embedding
    node_in_kernel<<<(NN + 3) / 4, 256>>>(x, Wn, bn);

    // 3) transformer conv layers
    for (int l = 0; l < NLAYER; l++) {
        prep_M_kernel<<<16, 256>>>(Wq, bq, We, l);
        qkvs_kernel<<<(NN + 63) / 64, 256, (64 * 64 + 64 * 320) * 4>>>(
            Wq, bq, Wk, bk, Wv, bv, Ws, bs, l);
        attn_kernel<<<(NN + 7) / 8, 256>>>(We, l);
    }

    // 4) fused mean pool + MLP head (batch is sorted)
    pool_mlp_kernel<<<GG, 1024>>>(bat, W1, b1, W2, b2, out);
}

// round 6
// speedup vs baseline: 1.0942x; 1.0942x over previous
#include <cuda_runtime.h>
#include <math.h>

#define NN 50000
#define EE 1600000
#define GG 64
#define NODE_IN 32
#define HID 64
#define EDGE_IN 16
#define NLAYER 3

// ---------------- device scratch (static globals; no runtime alloc) ----------------
__device__ float d_h[NN * HID];
__device__ float d_qn[NN * HID];
__device__ float d_kn[NN * HID];
__device__ float d_vn[NN * HID];
__device__ float d_sn[NN * HID];
__device__ float d_qwn[NN * HID];   // per-node q.We projection (4 heads x 16 r, packed)
__device__ int   d_deg[NN];
__device__ int   d_offs[NN + 1];
__device__ int   d_cursor[NN];
__device__ int   d_bsum[64];
__device__ int2  d_sedge[EE];       // {src, eid} sorted by dst
__device__ float d_M[HID * HID];    // fused Wq x We matrix for qw GEMM
__device__ float d_bqw[HID];

__device__ __forceinline__ float ex2(float x) {
    float r;
    asm("ex2.approx.f32 %0, %1;" : "=f"(r) : "f"(x));
    return r;
}

// ---------------- preprocessing: counting sort of edges by dst ----------------
__global__ void zero_deg_kernel() {
    int i = blockIdx.x * blockDim.x + threadIdx.x;
    if (i < NN) d_deg[i] = 0;
}

__global__ void hist_kernel(const int* __restrict__ ei) {
    int e = blockIdx.x * blockDim.x + threadIdx.x;
    if (e < EE) atomicAdd(&d_deg[ei[EE + e]], 1);
}

__global__ void scan1_kernel() {
    __shared__ int s[1024];
    int t = threadIdx.x;
    int i = blockIdx.x * 1024 + t;
    int v = (i < NN) ? d_deg[i] : 0;
    s[t] = v;
    __syncthreads();
    for (int o = 1; o < 1024; o <<= 1) {
        int x = (t >= o) ? s[t - o] : 0;
        __syncthreads();
        s[t] += x;
        __syncthreads();
    }
    if (i < NN) d_offs[i] = s[t] - v;
    if (t == 1023) d_bsum[blockIdx.x] = s[t];
}

// scan3 now also folds the cross-block prefix (former scan2): each block loads the
// <=64 block sums into smem and sums below its own block id.
__global__ void scan3_kernel(int nb) {
    __shared__ int pref[64];
    int t = threadIdx.x;
    if (t < nb) pref[t] = d_bsum[t];
    __syncthreads();
    int i = blockIdx.x * 256 + t;
    if (i < NN) {
        int b = i >> 10;
        int add = 0;
        for (int j = 0; j < b; j++) add += pref[j];
        int v = d_offs[i] + add;
        d_offs[i] = v;
        d_cursor[i] = v;
    }
    if (i == 0) {
        int tot = 0;
        for (int j = 0; j < nb; j++) tot += pref[j];
        d_offs[NN] = tot;   // == EE
    }
}

__global__ void scatter_kernel(const int* __restrict__ ei) {
    int e = blockIdx.x * blockDim.x + threadIdx.x;
    if (e < EE) {
        int dstv = ei[EE + e];
        int pos = atomicAdd(&d_cursor[dstv], 1);
        d_sedge[pos] = make_int2(ei[e], e);
    }
}

// ---------------- input embedding: h = relu(x @ Wn + bn) ----------------
__global__ __launch_bounds__(256) void node_in_kernel(const float* __restrict__ x,
                                                      const float* __restrict__ Wn,
                                                      const float* __restrict__ bn) {
    __shared__ float Wns[NODE_IN * HID];
    __shared__ float bns[HID];
    __shared__ float xs[4][NODE_IN];
    int t = threadIdx.x;
    for (int u = t; u < NODE_IN * HID; u += 256) Wns[u] = Wn[u];
    if (t < HID) bns[t] = bn[t];
    int j = t & 63, y = t >> 6;
    int node = blockIdx.x * 4 + y;
    if (j < NODE_IN && node < NN) xs[y][j] = x[node * NODE_IN + j];
    __syncthreads();
    if (node < NN) {
        float a = bns[j];
        #pragma unroll
        for (int k = 0; k < NODE_IN; k++) a += xs[y][k] * Wns[k * HID + j];
        d_h[(size_t)node * HID + j] = fmaxf(a, 0.f);
    }
}

// ---------------- per-layer M = per-head (Wq x We), bqw = per-head (bq x We) ------
__global__ void prep_M_kernel(const float* __restrict__ Wq, const float* __restrict__ bq,
                              const float* __restrict__ We, int layer) {
    int idx = blockIdx.x * 256 + threadIdx.x;
    const float* Wql = Wq + layer * HID * HID;
    const float* Wel = We + layer * EDGE_IN * HID;
    if (idx < HID * HID) {
        int krow = idx >> 6, col = idx & 63;
        int h = col >> 4, r = col & 15;
        float s = 0.f;
        #pragma unroll
        for (int c = 0; c < 16; c++)
            s += Wql[krow * HID + h * 16 + c] * Wel[r * HID + h * 16 + c];
        d_M[idx] = s;
    }
    if (idx < HID) {
        int h = idx >> 4, r = idx & 15;
        const float* bql = bq + layer * HID;
        float s = 0.f;
        #pragma unroll
        for (int c = 0; c < 16; c++)
            s += bql[h * 16 + c] * Wel[r * HID + h * 16 + c];
        d_bqw[idx] = s;
    }
}

// ---------------- fused Q/K/V/Skip/QW node GEMM (64 x 320 tile) -------------------
__global__ __launch_bounds__(256, 2) void qkvs_kernel(
    const float* __restrict__ Wq, const float* __restrict__ bq,
    const float* __restrict__ Wk, const float* __restrict__ bk,
    const float* __restrict__ Wv, const float* __restrict__ bv,
    const float* __restrict__ Ws, const float* __restrict__ bs, int layer) {
    extern __shared__ float sm[];
    float* hs = sm;            // 64 x 64
    float* ws = sm + 64 * 64;  // 64 x 320
    const float* Wm[5] = {Wq + layer * HID * HID, Wk + layer * HID * HID,
                          Wv + layer * HID * HID, Ws + layer * HID * HID, d_M};
    const float* bm[5] = {bq + layer * HID, bk + layer * HID, bv + layer * HID,
                          bs + layer * HID, d_bqw};
    float* outp[5] = {d_qn, d_kn, d_vn, d_sn, d_qwn};
    int t = threadIdx.x;
    int node0 = blockIdx.x * 64;

    #pragma unroll
    for (int u = 0; u < 20; u++) {
        int mat = u >> 2;
        int e0 = ((u & 3) * 256 + t) * 4;
        int k = e0 >> 6, jj = e0 & 63;
        float4 w4 = *reinterpret_cast<const float4*>(Wm[mat] + k * HID + jj);
        *reinterpret_cast<float4*>(ws + k * 320 + mat * 64 + jj) = w4;
    }
    #pragma unroll
    for (int u = 0; u < 4; u++) {
        int e0 = (u * 256 + t) * 4;
        int row = e0 >> 6, k = e0 & 63;
        int node = node0 + row;
        float4 h4 = make_float4(0.f, 0.f, 0.f, 0.f);
        if (node < NN) h4 = *reinterpret_cast<const float4*>(d_h + (size_t)node * HID + k);
        *reinterpret_cast<float4*>(hs + e0) = h4;
    }
    __syncthreads();

    int ry = t >> 5;
    int cx = t & 31;
    float acc[8][10];
    #pragma unroll
    for (int c = 0; c < 10; c++) {
        int mat = c >> 1;
        int jj = (c & 1) * 32 + cx;
        float b = bm[mat][jj];
        #pragma unroll
        for (int rr = 0; rr < 8; rr++) acc[rr][c] = b;
    }
    #pragma unroll 4
    for (int k0 = 0; k0 < 64; k0 += 4) {
        float4 hr4[8];
        #pragma unroll
        for (int rr = 0; rr < 8; rr++)
            hr4[rr] = *reinterpret_cast<const float4*>(hs + (ry * 8 + rr) * 64 + k0);
        #pragma unroll
        for (int kk = 0; kk < 4; kk++) {
            float wr[10];
            #pragma unroll
            for (int c = 0; c < 10; c++) wr[c] = ws[(k0 + kk) * 320 + cx + c * 32];
            #pragma unroll
            for (int rr = 0; rr < 8; rr++) {
                float hv = (kk == 0) ? hr4[rr].x : (kk == 1) ? hr4[rr].y
                         : (kk == 2) ? hr4[rr].z : hr4[rr].w;
                #pragma unroll
                for (int c = 0; c < 10; c++) acc[rr][c] += hv * wr[c];
            }
        }
    }
    #pragma unroll
    for (int rr = 0; rr < 8; rr++) {
        int node = node0 + ry * 8 + rr;
        if (node >= NN) continue;
        #pragma unroll
        for (int c = 0; c < 10; c++) {
            int mat = c >> 1;
            int jj = (c & 1) * 32 + cx;
            outp[mat][(size_t)node * HID + jj] = acc[rr][c];
        }
    }
}

// ---------------- fused attention: half-warp per edge, warp per node -------------
// lane = 16*hf + 4*head + p ; lane owns channels (4h+p)*4..+3, edge-feats p*4..+3.
// Two parallel softmax streams (one per half), merged at the end. Warp-uniform
// trip count; trailing invalid slot clamps loads and contributes w=0.
// d_sedge (src+eid, one 8B load) prefetched DEPTH 2; K/V/E depth 1 — removes the
// serial sedge->gather chain from the per-iteration critical path.
__global__ __launch_bounds__(256) void attn_kernel(const float* __restrict__ We,
                                                   const float* __restrict__ ea,
                                                   int layer) {
    __shared__ float WeS[16 * 68 + 4];  // skewed: [r*68 + col + (col>>4)]
    int t = threadIdx.x;
    const float* Wel = We + layer * EDGE_IN * HID;
    for (int u = t; u < EDGE_IN * HID; u += 256) {
        int r = u >> 6, col = u & 63;
        WeS[r * 68 + col + (col >> 4)] = Wel[u];
    }
    __syncthreads();

    int lane = t & 31;
    int warp = t >> 5;
    int n = blockIdx.x * 8 + warp;
    if (n >= NN) return;

    int hf = lane >> 4;
    int hl = lane & 15;
    int h = hl >> 2;
    int p = hl & 3;
    int cbs = hl * 4 + h;

    float4 q  = reinterpret_cast<const float4*>(d_qn)[n * 16 + hl];
    float4 qw = reinterpret_cast<const float4*>(d_qwn)[n * 16 + hl];

    float m = -1e30f, den = 0.f;
    float4 acc = make_float4(0.f, 0.f, 0.f, 0.f);
    float4 eac = make_float4(0.f, 0.f, 0.f, 0.f);

    int beg = d_offs[n], end = d_offs[n + 1];
    int d = end - beg;
    int itmax = (d + 1) >> 1;          // warp-uniform trip count

    int i = beg + hf;                  // current edge index for this stream
    bool vld_cur = (i < end);
    bool vld_nxt = (i + 2 < end);
    int2 se_nxt = make_int2(0, 0);
    float4 k4, v4, e4;
    if (itmax > 0) {
        int idx = vld_cur ? i : (end - 1);
        int2 se = d_sedge[idx];
        k4 = reinterpret_cast<const float4*>(d_kn)[se.x * 16 + hl];
        v4 = reinterpret_cast<const float4*>(d_vn)[se.x * 16 + hl];
        e4 = reinterpret_cast<const float4*>(ea)[se.y * 4 + p];
        if (itmax > 1) {
            int idx2 = vld_nxt ? (i + 2) : (end - 1);
            se_nxt = d_sedge[idx2];    // depth-2 prefetch of the index pair
        }
    }
    for (int it = 0; it < itmax; it++) {
        float4 ck = k4, cv = v4, ce = e4;
        bool cvld = vld_cur;
        if (it + 1 < itmax) {
            // gathers for it+1 use the ALREADY-RESIDENT se_nxt (no serial chain)
            k4 = reinterpret_cast<const float4*>(d_kn)[se_nxt.x * 16 + hl];
            v4 = reinterpret_cast<const float4*>(d_vn)[se_nxt.x * 16 + hl];
            e4 = reinterpret_cast<const float4*>(ea)[se_nxt.y * 4 + p];
            vld_cur = vld_nxt;
            int i4 = i + 4;            // prefetch index pair for it+2
            bool v4b = (i4 < end);
            int idx4 = v4b ? i4 : (end - 1);
            se_nxt = d_sedge[idx4];
            vld_nxt = v4b;
            i += 2;
        }
        float pp = q.x * ck.x + q.y * ck.y + q.z * ck.z + q.w * ck.w
                 + qw.x * ce.x + qw.y * ce.y + qw.z * ce.z + qw.w * ce.w;
        pp += __shfl_xor_sync(0xffffffffu, pp, 1);
        pp += __shfl_xor_sync(0xffffffffu, pp, 2);
        pp = cvld ? pp * 0.36067376022224085f : -1e30f;   // 0.25*log2(e); -inf if invalid
        float w;
        if (cvld && pp > m) {          // new running max (rare)
            float sc = ex2(m - pp);
            m = pp;
            den *= sc;
            acc.x *= sc; acc.y *= sc; acc.z *= sc; acc.w *= sc;
            eac.x *= sc; eac.y *= sc; eac.z *= sc; eac.w *= sc;
            w = 1.0f;
        } else {
            w = ex2(pp - m);           // invalid: pp-m=0 -> w=1, zeroed below
            w = cvld ? w : 0.f;
        }
        den += w;
        acc.x += w * cv.x; acc.y += w * cv.y; acc.z += w * cv.z; acc.w += w * cv.w;
        eac.x += w * ce.x; eac.y += w * ce.y; eac.z += w * ce.z; eac.w += w * ce.w;
    }

    // fold edge-embedding: acc[c] += sum_r eacc[h][r] * We[r][c]   (conflict-free smem)
    float ea_arr[4] = {eac.x, eac.y, eac.z, eac.w};
    #pragma unroll
    for (int r = 0; r < 16; r++) {
        float ev = __shfl_sync(0xffffffffu, ea_arr[r & 3], (h << 2) + (r >> 2), 16);
        acc.x += ev * WeS[r * 68 + cbs + 0];
        acc.y += ev * WeS[r * 68 + cbs + 1];
        acc.z += ev * WeS[r * 68 + cbs + 2];
        acc.w += ev * WeS[r * 68 + cbs + 3];
    }

    // merge the two half-warp softmax streams
    float om  = __shfl_xor_sync(0xffffffffu, m,    16);
    float odn = __shfl_xor_sync(0xffffffffu, den,  16);
    float oax = __shfl_xor_sync(0xffffffffu, acc.x, 16);
    float oay = __shfl_xor_sync(0xffffffffu, acc.y, 16);
    float oaz = __shfl_xor_sync(0xffffffffu, acc.z, 16);
    float oaw = __shfl_xor_sync(0xffffffffu, acc.w, 16);
    float mm = fmaxf(m, om);
    float sA = ex2(m - mm), sB = ex2(om - mm);
    den = den * sA + odn * sB;
    float ox = acc.x * sA + oax * sB;
    float oy = acc.y * sA + oay * sB;
    float oz = acc.z * sA + oaz * sB;
    float ow = acc.w * sA + oaw * sB;

    if (hf == 0) {
        float inv = 1.f / (den + 1e-16f);
        float4 s4 = reinterpret_cast<const float4*>(d_sn)[n * 16 + hl];
        float4 hc = reinterpret_cast<const float4*>(d_h)[n * 16 + hl];
        hc.x += fmaxf(ox * inv + s4.x, 0.f);
        hc.y += fmaxf(oy * inv + s4.y, 0.f);
        hc.z += fmaxf(oz * inv + s4.z, 0.f);
        hc.w += fmaxf(ow * inv + s4.w, 0.f);
        reinterpret_cast<float4*>(d_h)[n * 16 + hl] = hc;
    }
}

// ---------------- fused mean pool (sorted batch) + readout MLP -------------------
__global__ __launch_bounds__(1024) void pool_mlp_kernel(const int* __restrict__ batch,
    const float* __restrict__ W1, const float* __restrict__ b1,
    const float* __restrict__ W2, const float* __restrict__ b2,
    float* __restrict__ out) {
    __shared__ float red[1024];
    __shared__ float sp[64];
    __shared__ int bnd[2];
    int g = blockIdx.x, t = threadIdx.x;
    if (t == 0) {
        int lo = 0, hi = NN;
        while (lo < hi) { int mid = (lo + hi) >> 1; if (batch[mid] < g) lo = mid + 1; else hi = mid; }
        bnd[0] = lo;
        int lo2 = lo, hi2 = NN;
        while (lo2 < hi2) { int mid = (lo2 + hi2) >> 1; if (batch[mid] < g + 1) lo2 = mid + 1; else hi2 = mid; }
        bnd[1] = lo2;
    }
    __syncthreads();
    int lo = bnd[0], hi = bnd[1];
    int ch = t & 63, rg = t >> 6;     // 16 row groups
    float a = 0.f;
    for (int nd = lo + rg; nd < hi; nd += 16) a += d_h[(size_t)nd * HID + ch];
    red[t] = a;
    __syncthreads();
    if (t < 64) {
        float s = 0.f;
        #pragma unroll
        for (int j = 0; j < 16; j++) s += red[t + 64 * j];
        sp[t] = s / fmaxf((float)(hi - lo), 1.0f);
    }
    __syncthreads();
    if (t < 32) {
        float accv = b1[t];
        #pragma unroll
        for (int k = 0; k < HID; k++) accv += sp[k] * W1[k * 32 + t];
        float v = fmaxf(accv, 0.f) * W2[t];
        #pragma unroll
        for (int o = 16; o; o >>= 1) v += __shfl_xor_sync(0xffffffffu, v, o);
        if (t == 0) out[g] = v + b2[0];
    }
}

// ---------------- launch ----------------
extern "C" void kernel_launch(void* const* d_in, const int* in_sizes, int n_in,
                              void* d_out, int out_size) {
    const float* x   = (const float*)d_in[0];
    const int*   ei  = (const int*)d_in[1];
    const float* ea  = (const float*)d_in[2];
    const int*   bat = (const int*)d_in[3];
    const float* Wn  = (const float*)d_in[4];
    const float* bn  = (const float*)d_in[5];
    const float* Wq  = (const float*)d_in[6];
    const float* bq  = (const float*)d_in[7];
    const float* Wk  = (const float*)d_in[8];
    const float* bk  = (const float*)d_in[9];
    const float* Wv  = (const float*)d_in[10];
    const float* bv  = (const float*)d_in[11];
    const float* We  = (const float*)d_in[12];
    const float* Ws  = (const float*)d_in[13];
    const float* bs  = (const float*)d_in[14];
    const float* W1  = (const float*)d_in[15];
    const float* b1  = (const float*)d_in[16];
    const float* W2  = (const float*)d_in[17];
    const float* b2  = (const float*)d_in[18];
    float* out = (float*)d_out;

    cudaFuncSetAttribute(qkvs_kernel, cudaFuncAttributeMaxDynamicSharedMemorySize, 100 * 1024);

    // 1) counting sort of edges by dst -> CSR of {src, eid}
    zero_deg_kernel<<<(NN + 255) / 256, 256>>>();
    hist_kernel<<<(EE + 255) / 256, 256>>>(ei);
    int nb = (NN + 1023) / 1024;
    scan1_kernel<<<nb, 1024>>>();
    scan3_kernel<<<(NN + 255) / 256, 256>>>(nb);
    scatter_kernel<<<(EE + 255) / 256, 256>>>(ei);

    // 2) input embedding
    node_in_kernel<<<(NN + 3) / 4, 256>>>(x, Wn, bn);

    // 3) transformer conv layers
    for (int l = 0; l < NLAYER; l++) {
        prep_M_kernel<<<16, 256>>>(Wq, bq, We, l);
        qkvs_kernel<<<(NN + 63) / 64, 256, (64 * 64 + 64 * 320) * 4>>>(
            Wq, bq, Wk, bk, Wv, bv, Ws, bs, l);
        attn_kernel<<<(NN + 7) / 8, 256>>>(We, ea, l);
    }

    // 4) fused mean pool + MLP head (batch is sorted)
    pool_mlp_kernel<<<GG, 1024>>>(bat, W1, b1, W2, b2, out);
}